// round 12
// baseline (speedup 1.0000x reference)
#include <cuda_runtime.h>
#include <math.h>

// DBN beat decoder (bar-pointer Viterbi). B=4, T=6000, 82 blocks, S=5617.
//
// R11: 28-step window fusion. Since min interval tau=28, any path beats at most
// once per 28-step window, so delta(t+28) is a direct function of delta(t):
//   pos>=28: delta(t)[s-28] + nb(t+1)+...+nb(t+28)   (sequential adds, bit-exact)
//   L-table: L(t+q)[i] = delta(t)[last_i - q] + nb-prefix (q=0..27), one phase
//   pos p<28: vf(t+28-p) + nb suffix; vf computed by 28 independent reductions,
//             each leader chains its suffix and stores the output cell directly.
// Two barriers per window (vs 2 per 2 steps in R10). No cross-window scratch.
// Backpointers compressed to g_plbuf rows (= L table); argmax recomputed at
// ~90 beat jumps during backtracking (first-index tiebreak => identical path).

#define NI      82
#define MINTAU  28
#define NSTATE  5617
#define TT      6000
#define BB      4
#define NTHREADS 768
#define NSLOTS  8       // 768*8 = 6144 >= 5617
#define WIN     28
#define NWIN    214     // 214*28 = 5992
#define TAILW   7       // 5992 + 7 = 5999 steps

// shared layout (float offsets). Buffers placed after TL so that the bulk's
// unmasked loads at [buf - 28 .. buf) land in valid shared (TL tail / buffer A).
#define OFF_TL   0          // trans_log 82x82          (6724)
#define OFF_A    6752       // delta buffer A           (6144)
#define OFF_B    12896      // delta buffer B           (6144)
#define OFF_BLP  19040      // beat logprob             (6000)
#define OFF_NB   25040      // nonbeat logprob          (6000)
#define OFF_L    31040      // L table 28 rows x 96     (2688; cols 82..95 = -inf)
#define OFF_RV   33728      // argmax values            (768)
#define OFF_RI   34496      // argmax indices           (768)
#define SM_FLOATS 35264

__device__ float g_plbuf[BB][TT + 1][NI];

__device__ __forceinline__ int base_of(int j) {
    return MINTAU * j + (j * (j - 1)) / 2;
}

// One fused window: delta(t) at sm[po..] -> delta(t+W) at sm[no..].
template<int W>
__device__ __forceinline__ void do_window(float* sm, int b, int t, int po, int no,
        int tid, int wrp, int rj, int rg, int baseRJ, unsigned geM, const float* tlr)
{
    __syncthreads();   // prev window's outputs (po buffer) complete

    // ---- phase 1a: L-table chains (82*W entries) + backtrack rows ----
    #pragma unroll
    for (int m = 0; m < 3; ++m) {
        int p = 3 * tid + m;
        if (p < NI * W) {
            int q = p / NI;                 // 0..W-1
            int i = p - NI * q;             // 0..81
            int last = MINTAU * (i + 1) + ((i + 1) * i) / 2 - 1;
            float val = sm[po + last - q];
            for (int r = 1; r <= q; ++r) val += sm[OFF_NB + t + r];
            sm[OFF_L + q * 96 + i] = val;
            g_plbuf[b][t + q + 1][i] = val;
        }
    }
    // ---- phase 1b: bulk shift-by-W (pos>=W cells; stores predicated) ----
    {
        float x[NSLOTS];
        #pragma unroll
        for (int k = 0; k < NSLOTS; ++k) x[k] = sm[po + tid + k * NTHREADS - W];
        #pragma unroll
        for (int r = 1; r <= W; ++r) {
            float nbr = sm[OFF_NB + t + r];
            #pragma unroll
            for (int k = 0; k < NSLOTS; ++k) x[k] += nbr;
        }
        #pragma unroll
        for (int k = 0; k < NSLOTS; ++k)
            if ((geM >> k) & 1u) sm[no + tid + k * NTHREADS] = x[k];
    }
    __syncthreads();   // L table + bulk cells ready

    // ---- phase 2: W independent reductions; leaders chain + store pos<W ----
    if (wrp < 21) {
        #pragma unroll 4
        for (int q = 1; q <= W; ++q) {
            const int lrow = OFF_L + (q - 1) * 96;
            const float4 a0 = *(const float4*)&sm[lrow + 4 * rg];
            const float4 a1 = *(const float4*)&sm[lrow + 32 + 4 * rg];
            const float4 a2 = *(const float4*)&sm[lrow + 64 + 4 * rg];
            float p0 = a0.x + tlr[0], p1 = a0.y + tlr[1];
            p0 = fmaxf(p0, a0.z + tlr[2]);  p1 = fmaxf(p1, a0.w + tlr[3]);
            p0 = fmaxf(p0, a1.x + tlr[4]);  p1 = fmaxf(p1, a1.y + tlr[5]);
            p0 = fmaxf(p0, a1.z + tlr[6]);  p1 = fmaxf(p1, a1.w + tlr[7]);
            p0 = fmaxf(p0, a2.x + tlr[8]);  p1 = fmaxf(p1, a2.y + tlr[9]);
            p0 = fmaxf(p0, a2.z + tlr[10]); p1 = fmaxf(p1, a2.w + tlr[11]);
            float best = fmaxf(p0, p1);
            best = fmaxf(best, __shfl_xor_sync(0xffffffffu, best, 1));
            best = fmaxf(best, __shfl_xor_sync(0xffffffffu, best, 2));
            best = fmaxf(best, __shfl_xor_sync(0xffffffffu, best, 4));
            if (rg == 0 && rj < NI) {
                float vf = best + sm[OFF_BLP + t + q];     // beat entry at t+q
                for (int r = q + 1; r <= W; ++r) vf += sm[OFF_NB + t + r];
                sm[no + baseRJ + (W - q)] = vf;            // pos = W-q at t+W
            }
        }
    }
}

__global__ void __launch_bounds__(NTHREADS, 1)
dbn_viterbi_kernel(const float* __restrict__ logit, float* __restrict__ out)
{
    extern __shared__ float sm[];
    const int tid = threadIdx.x;
    const int wrp = tid >> 5;
    const int b   = blockIdx.x;
    const float* lg = logit + b * TT;
    float* outrow   = out + b * TT;

    const float NEGINF = __int_as_float(0xff800000);

    // ---- zero output row ----
    for (int t = tid; t < TT; t += NTHREADS) outrow[t] = 0.0f;

    // ---- emissions (double precision, cast to f32; bit-matched reference) ----
    for (int t = tid; t < TT; t += NTHREADS) {
        double x = (double)lg[t];
        double bl = (x >= 0.0) ? -log1p(exp(-x)) : (x - log1p(exp(x)));
        double nl = (x <= 0.0) ? -log1p(exp(x))  : (-x - log1p(exp(-x)));
        sm[OFF_BLP + t] = (float)bl;
        sm[OFF_NB  + t] = (float)nl;
    }

    // ---- trans_log rows (double precision log-softmax) ----
    if (tid < NI) {
        int i = tid;
        double ti = (double)(MINTAU + i);
        double ssum = 0.0;
        for (int j = 0; j < NI; ++j) {
            double r = -100.0 * fabs((double)(MINTAU + j) / ti - 1.0);
            ssum += exp(r);
        }
        double ls = log(ssum);  // row max is 0 (at j==i)
        for (int j = 0; j < NI; ++j) {
            double r = -100.0 * fabs((double)(MINTAU + j) / ti - 1.0);
            sm[OFF_TL + i * NI + j] = (float)(r - ls);
        }
    }
    // -inf pads for all L rows (cols 82..95), set once
    if (tid < WIN * 14) {
        int row = tid / 14, c = tid % 14;
        sm[OFF_L + row * 96 + 82 + c] = NEGINF;
    }

    // ---- per-slot metadata ----
    unsigned firstM = 0, validM = 0, ge28M = 0, ge7M = 0;
    #pragma unroll
    for (int k = 0; k < NSLOTS; ++k) {
        int s = tid + k * NTHREADS;
        int j = 0;
        while (j < NI - 1 && base_of(j + 1) <= s) ++j;
        int pos = s - base_of(j);
        bool valid = (s < NSTATE);
        if (valid) validM |= 1u << k;
        if (valid && pos == 0) firstM |= 1u << k;
        if (!valid || pos >= WIN)   ge28M |= 1u << k;   // pads: store garbage to pad cells
        if (!valid || pos >= TAILW) ge7M  |= 1u << k;
    }

    const float logS = (float)log((double)NSTATE);

    __syncthreads();   // tables ready

    // ---- preload trans_log candidates (8 lanes per j-group, padded to 96 groups) ----
    const int rj = tid >> 3, rg = tid & 7;
    const int baseRJ = (rj < NI) ? base_of(rj) : 0;
    float tlr[12];
    #pragma unroll
    for (int q = 0; q < 12; ++q) {
        int i = 4 * rg + 32 * (q >> 2) + (q & 3);
        tlr[q] = (rj < NI && i < NI) ? sm[OFF_TL + i * NI + rj] : 0.0f;  // L pad = -inf
    }

    // ---- init delta(0) into buffer A ----
    {
        float bt0 = sm[OFF_BLP + 0], nbt0 = sm[OFF_NB + 0];
        #pragma unroll
        for (int k = 0; k < NSLOTS; ++k) {
            int s = tid + k * NTHREADS;
            float em = ((firstM >> k) & 1u) ? bt0 : nbt0;
            sm[OFF_A + s] = em - logS;   // pads finite, harmless
        }
    }

    // ---- forward: 214 windows of 28 + one tail window of 7 ----
    int po = OFF_A, no = OFF_B;
    #pragma unroll 1
    for (int wnd = 0; wnd < NWIN; ++wnd) {
        do_window<WIN>(sm, b, wnd * WIN, po, no, tid, wrp, rj, rg, baseRJ, ge28M, tlr);
        int tmp = po; po = no; no = tmp;
    }
    // after 214 swaps (even): po = OFF_A. Tail: delta(5992) -> delta(5999) in OFF_B.
    do_window<TAILW>(sm, b, NWIN * WIN, po, no, tid, wrp, rj, rg, baseRJ, ge7M, tlr);
    __syncthreads();

    // ---- final argmax over delta(5999) in OFF_B, first-index tiebreak ----
    {
        float bv = NEGINF; int bs = NSTATE - 1;
        #pragma unroll
        for (int k = 0; k < NSLOTS; ++k) {
            if ((validM >> k) & 1u) {
                int s = tid + k * NTHREADS;
                float val = sm[OFF_B + s];
                if (val > bv) { bv = val; bs = s; }
            }
        }
        sm[OFF_RV + tid] = bv;
        ((int*)sm)[OFF_RI + tid] = bs;
    }
    __syncthreads();
    if (tid < NTHREADS - 512) {   // fold 512..767 into 0..255
        float v2 = sm[OFF_RV + tid + 512]; int s2 = ((int*)sm)[OFF_RI + tid + 512];
        if (v2 > sm[OFF_RV + tid] ||
            (v2 == sm[OFF_RV + tid] && s2 < ((int*)sm)[OFF_RI + tid])) {
            sm[OFF_RV + tid] = v2; ((int*)sm)[OFF_RI + tid] = s2;
        }
    }
    __syncthreads();
    for (int st = 256; st > 0; st >>= 1) {
        if (tid < st) {
            float v2 = sm[OFF_RV + tid + st]; int s2 = ((int*)sm)[OFF_RI + tid + st];
            if (v2 > sm[OFF_RV + tid] ||
                (v2 == sm[OFF_RV + tid] && s2 < ((int*)sm)[OFF_RI + tid])) {
                sm[OFF_RV + tid] = v2; ((int*)sm)[OFF_RI + tid] = s2;
            }
        }
        __syncthreads();
    }

    // ---- backtrack (thread 0): jump beat-to-beat, hard-bounded ----
    if (tid == 0) {
        const double p0  = (double)0.05f;
        const double thr = log(p0 / (1.0 - p0));   // logit-space threshold

        int s = ((int*)sm)[OFF_RI + 0];
        if (s < 0) s = 0;
        if (s >= NSTATE) s = NSTATE - 1;
        int j = 0;
        while (j < NI - 1 && base_of(j + 1) <= s) ++j;
        int p = s - base_of(j);
        int t = TT - 1;
        for (int iter = 0; iter < TT; ++iter) {
            if (p > t) break;            // path started mid-block: no beat
            int tb = t - p;              // beat time (position 0)
            double x = (double)lg[tb];
            outrow[tb] = (x >= thr) ? 1.0f : 0.0f;
            if (tb == 0) break;
            const float* row = &g_plbuf[b][tb][0];
            float mx = NEGINF; int bi = 0;
            for (int i = 0; i < NI; ++i) {
                float c = row[i] + sm[OFF_TL + i * NI + j];
                if (c > mx) { mx = c; bi = i; }
            }
            j = bi;
            t = tb - 1;
            p = (MINTAU + j) - 1;
        }
    }
}

extern "C" void kernel_launch(void* const* d_in, const int* in_sizes, int n_in,
                              void* d_out, int out_size)
{
    const float* logit = (const float*)d_in[0];
    float* out = (float*)d_out;

    size_t smem = (size_t)SM_FLOATS * sizeof(float);   // 141,056 B
    cudaFuncSetAttribute(dbn_viterbi_kernel,
                         cudaFuncAttributeMaxDynamicSharedMemorySize, (int)smem);
    dbn_viterbi_kernel<<<BB, NTHREADS, smem>>>(logit, out);
}

// round 13
// speedup vs baseline: 1.2725x; 1.2725x over previous
#include <cuda_runtime.h>
#include <math.h>
#include <stdint.h>

// DBN beat decoder (bar-pointer Viterbi). B=4, T=6000, 82 blocks, S=5617.
//
// R13: 28-step window, 3 phases, 3 barriers/window:
//  P1: bulk shift-by-28 with packed f32x2 adds (pos>=28) + L-table rows
//      (q-uniform warps, float4-chunked nb chains) + g_plbuf backtrack rows.
//  P2: 28 independent 82x82 max-plus reductions (21 warps, 12 contiguous
//      candidates/lane, 3 LDS.128, 3 shuffles); leaders store RAW vf(+blp).
//  P3: 2296 pos<28 output cells: suffix chains, p-uniform warps.
// All f32 adds strictly sequential in time order => bit-identical to reference.
// Backpointers compressed to g_plbuf; argmax recomputed at ~90 beat jumps.

#define NI      82
#define MINTAU  28
#define NSTATE  5617
#define TT      6000
#define BB      4
#define NTHREADS 768
#define WIN     28
#define NWIN    214     // 214*28 = 5992
#define TAILW   7       // +7 = 5999 steps

#define OFF_TL   0          // trans_log 82x82           (6724)
#define OFF_A    6752       // delta buffer A            (6144)
#define OFF_B    12896      // delta buffer B            (6144)
#define OFF_BLP  19040      // beat logprob              (6000)
#define OFF_NB   25040      // nonbeat logprob           (6000)
#define OFF_L    31040      // L table 28 x 96           (2688; cols82..95=-inf)
#define OFF_VF   33728      // vf_raw table 28 x 96      (2688)
#define OFF_RV   36416      // argmax values             (768)
#define OFF_RI   37184      // argmax indices            (768)
#define SM_FLOATS 37952

#define PACK2(out, lo, hi) asm("mov.b64 %0, {%1, %2};" : "=l"(out) : "f"(lo), "f"(hi))
#define UNPACK2(lo, hi, in) asm("mov.b64 {%0, %1}, %2;" : "=f"(lo), "=f"(hi) : "l"(in))
#define ADD2(out, a, b) asm("add.rn.f32x2 %0, %1, %2;" : "=l"(out) : "l"(a), "l"(b))

__device__ float g_plbuf[BB][TT + 1][NI];

__device__ __forceinline__ int base_of(int j) {
    return MINTAU * j + (j * (j - 1)) / 2;
}

// chained adds of nb[t+x0 .. t+x1] onto val, float4-chunked (bit-exact order).
__device__ __forceinline__ float nb_chain(const float* sm, int t, int x0, int x1, float val) {
    int x = x0;
    for (; x <= x1 && ((t + x) & 3); ++x) val += sm[OFF_NB + t + x];
    for (; x + 3 <= x1; x += 4) {
        float4 f = *(const float4*)&sm[OFF_NB + t + x];
        val += f.x; val += f.y; val += f.z; val += f.w;
    }
    for (; x <= x1; ++x) val += sm[OFF_NB + t + x];
    return val;
}

template<int W, int NPASS>
__device__ __forceinline__ void do_window(float* sm, int b, int t, int po, int no,
        int tid, int wrp, int wgrp, int li, int lastLi, int baseLi,
        int rj, int rg, const float* tlr, unsigned geM)
{
    __syncthreads();   // prev window complete in po

    // ---- P1a: bulk shift-by-W, packed f32x2 chain, masked stores ----
    {
        float l0 = sm[po + tid              - W], l1 = sm[po + tid + 1*NTHREADS - W];
        float l2 = sm[po + tid + 2*NTHREADS - W], l3 = sm[po + tid + 3*NTHREADS - W];
        float l4 = sm[po + tid + 4*NTHREADS - W], l5 = sm[po + tid + 5*NTHREADS - W];
        float l6 = sm[po + tid + 6*NTHREADS - W], l7 = sm[po + tid + 7*NTHREADS - W];
        uint64_t y0, y1, y2, y3;
        PACK2(y0, l0, l1); PACK2(y1, l2, l3); PACK2(y2, l4, l5); PACK2(y3, l6, l7);
        #pragma unroll
        for (int r = 1; r <= W; ++r) {
            float nb = sm[OFF_NB + t + r];
            uint64_t nb2; PACK2(nb2, nb, nb);
            ADD2(y0, y0, nb2); ADD2(y1, y1, nb2); ADD2(y2, y2, nb2); ADD2(y3, y3, nb2);
        }
        UNPACK2(l0, l1, y0); UNPACK2(l2, l3, y1);
        UNPACK2(l4, l5, y2); UNPACK2(l6, l7, y3);
        if (geM & 0x01u) sm[no + tid             ] = l0;
        if (geM & 0x02u) sm[no + tid + 1*NTHREADS] = l1;
        if (geM & 0x04u) sm[no + tid + 2*NTHREADS] = l2;
        if (geM & 0x08u) sm[no + tid + 3*NTHREADS] = l3;
        if (geM & 0x10u) sm[no + tid + 4*NTHREADS] = l4;
        if (geM & 0x20u) sm[no + tid + 5*NTHREADS] = l5;
        if (geM & 0x40u) sm[no + tid + 6*NTHREADS] = l6;
        if (geM & 0x80u) sm[no + tid + 7*NTHREADS] = l7;
    }
    // ---- P1b: L-table rows (q-uniform warps: 3 warps per row) ----
    #pragma unroll
    for (int h = 0; h < NPASS; ++h) {
        int r = 8 * h + wgrp;
        if (r < W && li < NI) {
            float val = nb_chain(sm, t, 1, r, sm[po + lastLi - r]);
            sm[OFF_L + r * 96 + li] = val;
            g_plbuf[b][t + r + 1][li] = val;
        }
    }
    __syncthreads();   // L table + bulk cells ready

    // ---- P2: W reductions; leaders store raw vf(+blp) to scratch ----
    if (wrp < 21) {
        #pragma unroll 4
        for (int q = 1; q <= W; ++q) {
            const float* Lr = &sm[OFF_L + (q - 1) * 96 + 12 * rg];
            const float4 a0 = *(const float4*)(Lr);
            const float4 a1 = *(const float4*)(Lr + 4);
            const float4 a2 = *(const float4*)(Lr + 8);
            float c0 = a0.x + tlr[0],  c1 = a0.y + tlr[1];
            float c2 = a0.z + tlr[2],  c3 = a0.w + tlr[3];
            c0 = fmaxf(c0, a1.x + tlr[4]);  c1 = fmaxf(c1, a1.y + tlr[5]);
            c2 = fmaxf(c2, a1.z + tlr[6]);  c3 = fmaxf(c3, a1.w + tlr[7]);
            c0 = fmaxf(c0, a2.x + tlr[8]);  c1 = fmaxf(c1, a2.y + tlr[9]);
            c2 = fmaxf(c2, a2.z + tlr[10]); c3 = fmaxf(c3, a2.w + tlr[11]);
            float best = fmaxf(fmaxf(c0, c1), fmaxf(c2, c3));
            best = fmaxf(best, __shfl_xor_sync(0xffffffffu, best, 1));
            best = fmaxf(best, __shfl_xor_sync(0xffffffffu, best, 2));
            best = fmaxf(best, __shfl_xor_sync(0xffffffffu, best, 4));
            if (rg == 0 && rj < NI)
                sm[OFF_VF + (q - 1) * 96 + rj] = best + sm[OFF_BLP + t + q];
        }
    }
    __syncthreads();   // vf_raw ready

    // ---- P3: pos<W output cells (p-uniform warps), suffix chains ----
    #pragma unroll
    for (int h = 0; h < NPASS; ++h) {
        int p = 8 * h + wgrp;
        if (p < W && li < NI) {
            float val = sm[OFF_VF + (W - 1 - p) * 96 + li];   // beat at t+W-p
            val = nb_chain(sm, t, W - p + 1, W, val);
            sm[no + baseLi + p] = val;
        }
    }
}

__global__ void __launch_bounds__(NTHREADS, 1)
dbn_viterbi_kernel(const float* __restrict__ logit, float* __restrict__ out)
{
    extern __shared__ float sm[];
    const int tid  = threadIdx.x;
    const int wrp  = tid >> 5;
    const int b    = blockIdx.x;
    const float* lg = logit + b * TT;
    float* outrow   = out + b * TT;

    const float NEGINF = __int_as_float(0xff800000);

    // ---- zero output row ----
    for (int t = tid; t < TT; t += NTHREADS) outrow[t] = 0.0f;

    // ---- emissions (double precision, cast to f32; bit-matched reference) ----
    for (int t = tid; t < TT; t += NTHREADS) {
        double x = (double)lg[t];
        double bl = (x >= 0.0) ? -log1p(exp(-x)) : (x - log1p(exp(x)));
        double nl = (x <= 0.0) ? -log1p(exp(x))  : (-x - log1p(exp(-x)));
        sm[OFF_BLP + t] = (float)bl;
        sm[OFF_NB  + t] = (float)nl;
    }

    // ---- trans_log rows (double precision log-softmax) ----
    if (tid < NI) {
        int i = tid;
        double ti = (double)(MINTAU + i);
        double ssum = 0.0;
        for (int j = 0; j < NI; ++j) {
            double r = -100.0 * fabs((double)(MINTAU + j) / ti - 1.0);
            ssum += exp(r);
        }
        double ls = log(ssum);  // row max is 0 (at j==i)
        for (int j = 0; j < NI; ++j) {
            double r = -100.0 * fabs((double)(MINTAU + j) / ti - 1.0);
            sm[OFF_TL + i * NI + j] = (float)(r - ls);
        }
    }
    // -inf pads for all L rows (cols 82..95), set once (P1b writes cols<82 only)
    if (tid < WIN * 14) {
        int row = tid / 14, c = tid % 14;
        sm[OFF_L + row * 96 + 82 + c] = NEGINF;
    }

    // ---- per-slot masks ----
    unsigned firstM = 0, validM = 0, ge28M = 0, ge7M = 0;
    #pragma unroll
    for (int k = 0; k < 8; ++k) {
        int s = tid + k * NTHREADS;
        int j = 0;
        while (j < NI - 1 && base_of(j + 1) <= s) ++j;
        int pos = s - base_of(j);
        bool valid = (s < NSTATE);
        if (valid) validM |= 1u << k;
        if (valid && pos == 0) firstM |= 1u << k;
        if (!valid || pos >= WIN)   ge28M |= 1u << k;
        if (!valid || pos >= TAILW) ge7M  |= 1u << k;
    }

    // per-thread roles
    const int wgrp   = tid / 96;                     // 0..7 (3 warps per group)
    const int li     = tid - 96 * wgrp;              // 0..95
    const int lastLi = (li < NI) ? (base_of(li + 1) - 1) : 0;
    const int baseLi = (li < NI) ? base_of(li) : 0;
    const int rj = tid >> 3, rg = tid & 7;           // reduction: 8 lanes per j

    const float logS = (float)log((double)NSTATE);

    __syncthreads();   // tables ready

    // ---- preload trans_log candidates: contiguous block i in [12rg, 12rg+12) ----
    float tlr[12];
    #pragma unroll
    for (int c = 0; c < 12; ++c) {
        int i = 12 * rg + c;
        tlr[c] = (rj < NI && i < NI) ? sm[OFF_TL + i * NI + rj] : 0.0f;  // L pad = -inf
    }

    // ---- init delta(0) into buffer A ----
    {
        float bt0 = sm[OFF_BLP + 0], nbt0 = sm[OFF_NB + 0];
        #pragma unroll
        for (int k = 0; k < 8; ++k) {
            int s = tid + k * NTHREADS;
            float em = ((firstM >> k) & 1u) ? bt0 : nbt0;
            sm[OFF_A + s] = em - logS;   // pads finite, harmless
        }
    }

    // ---- forward: 214 windows of 28 + tail of 7 ----
    int po = OFF_A, no = OFF_B;
    #pragma unroll 1
    for (int wnd = 0; wnd < NWIN; ++wnd) {
        do_window<WIN, 4>(sm, b, wnd * WIN, po, no, tid, wrp, wgrp, li,
                          lastLi, baseLi, rj, rg, tlr, ge28M);
        int tmp = po; po = no; no = tmp;
    }
    // po = OFF_A after 214 swaps; tail -> delta(5999) in OFF_B
    do_window<TAILW, 1>(sm, b, NWIN * WIN, po, no, tid, wrp, wgrp, li,
                        lastLi, baseLi, rj, rg, tlr, ge7M);
    __syncthreads();

    // ---- final argmax over delta(5999) in OFF_B, first-index tiebreak ----
    {
        float bv = NEGINF; int bs = NSTATE - 1;
        #pragma unroll
        for (int k = 0; k < 8; ++k) {
            if ((validM >> k) & 1u) {
                int s = tid + k * NTHREADS;
                float val = sm[OFF_B + s];
                if (val > bv) { bv = val; bs = s; }
            }
        }
        sm[OFF_RV + tid] = bv;
        ((int*)sm)[OFF_RI + tid] = bs;
    }
    __syncthreads();
    if (tid < NTHREADS - 512) {   // fold 512..767 into 0..255
        float v2 = sm[OFF_RV + tid + 512]; int s2 = ((int*)sm)[OFF_RI + tid + 512];
        if (v2 > sm[OFF_RV + tid] ||
            (v2 == sm[OFF_RV + tid] && s2 < ((int*)sm)[OFF_RI + tid])) {
            sm[OFF_RV + tid] = v2; ((int*)sm)[OFF_RI + tid] = s2;
        }
    }
    __syncthreads();
    for (int st = 256; st > 0; st >>= 1) {
        if (tid < st) {
            float v2 = sm[OFF_RV + tid + st]; int s2 = ((int*)sm)[OFF_RI + tid + st];
            if (v2 > sm[OFF_RV + tid] ||
                (v2 == sm[OFF_RV + tid] && s2 < ((int*)sm)[OFF_RI + tid])) {
                sm[OFF_RV + tid] = v2; ((int*)sm)[OFF_RI + tid] = s2;
            }
        }
        __syncthreads();
    }

    // ---- backtrack (thread 0): jump beat-to-beat, hard-bounded ----
    if (tid == 0) {
        const double p0  = (double)0.05f;
        const double thr = log(p0 / (1.0 - p0));   // logit-space threshold

        int s = ((int*)sm)[OFF_RI + 0];
        if (s < 0) s = 0;
        if (s >= NSTATE) s = NSTATE - 1;
        int j = 0;
        while (j < NI - 1 && base_of(j + 1) <= s) ++j;
        int p = s - base_of(j);
        int t = TT - 1;
        for (int iter = 0; iter < TT; ++iter) {
            if (p > t) break;            // path started mid-block: no beat
            int tb = t - p;              // beat time (position 0)
            double x = (double)lg[tb];
            outrow[tb] = (x >= thr) ? 1.0f : 0.0f;
            if (tb == 0) break;
            const float* row = &g_plbuf[b][tb][0];
            float mx = NEGINF; int bi = 0;
            for (int i = 0; i < NI; ++i) {
                float c = row[i] + sm[OFF_TL + i * NI + j];
                if (c > mx) { mx = c; bi = i; }
            }
            j = bi;
            t = tb - 1;
            p = (MINTAU + j) - 1;
        }
    }
}

extern "C" void kernel_launch(void* const* d_in, const int* in_sizes, int n_in,
                              void* d_out, int out_size)
{
    const float* logit = (const float*)d_in[0];
    float* out = (float*)d_out;

    size_t smem = (size_t)SM_FLOATS * sizeof(float);   // 151,808 B
    cudaFuncSetAttribute(dbn_viterbi_kernel,
                         cudaFuncAttributeMaxDynamicSharedMemorySize, (int)smem);
    dbn_viterbi_kernel<<<BB, NTHREADS, smem>>>(logit, out);
}

// round 15
// speedup vs baseline: 1.3910x; 1.0932x over previous
#include <cuda_runtime.h>
#include <math.h>
#include <stdint.h>

// DBN beat decoder (bar-pointer Viterbi). B=4, T=6000, 82 blocks, S=5617.
//
// R14: 28-step window (3 phases / 3 barriers) with instruction surgery:
//  - P1b/P3 nb-chains fully static (switch(wgrp) -> templates; t%4==0 always
//    so float4 chunking is compile-time). Straight-line FADD chains.
//  - P1a bulk: packed f32x2 adds, nb pairs preloaded from nbdup (LDS.64),
//    unconditional stores (P3 overwrites pos<28 cells later in the window).
//  - P2: 28 reductions, unroll 7, store predicate rg==0 only.
// All f32 adds strictly sequential in time order => bit-identical to reference.
// Backpointers compressed to g_plbuf; argmax recomputed at ~90 beat jumps.

#define NI      82
#define MINTAU  28
#define NSTATE  5617
#define TT      6000
#define BB      4
#define NTHREADS 768
#define WIN     28
#define NWIN    214     // 214*28 = 5992
#define TAILW   7       // +7 = 5999 steps

#define OFF_TL   0          // trans_log 82x82           (6724)
#define OFF_A    6752       // delta buffer A            (6144)
#define OFF_B    12896      // delta buffer B            (6144)
#define OFF_BLP  19040      // beat logprob              (6000)
#define OFF_NB   25040      // nonbeat logprob           (6000)
#define OFF_ND   31040      // packed (nb,nb) pairs      (12000)
#define OFF_L    43040      // L table 28 x 96           (2688; cols82..95=-inf)
#define OFF_VF   45728      // vf_raw table 28 x 96      (2688)
#define OFF_RV   48416      // argmax values             (768)
#define OFF_RI   49184      // argmax indices            (768)
#define SM_FLOATS 49952     // 199,808 bytes

#define PACK2(out, lo, hi) asm("mov.b64 %0, {%1, %2};" : "=l"(out) : "f"(lo), "f"(hi))
#define UNPACK2(lo, hi, in) asm("mov.b64 {%0, %1}, %2;" : "=f"(lo), "=f"(hi) : "l"(in))
#define ADD2(out, a, b) asm("add.rn.f32x2 %0, %1, %2;" : "=l"(out) : "l"(a), "l"(b))

__device__ float g_plbuf[BB][TT + 1][NI];

__device__ __forceinline__ int base_of(int j) {
    return MINTAU * j + (j * (j - 1)) / 2;
}

// Sequential adds of nbt[X0..X1] onto val (bit-exact order), statically
// chunked into float4 loads. Requires nbt 16B-aligned (t % 4 == 0).
template<int X0, int X1>
__device__ __forceinline__ float chain(const float* __restrict__ nbt, float val) {
    if constexpr (X1 >= X0) {
        constexpr int A0   = (X0 % 4 == 0) ? X0 : X0 + (4 - X0 % 4);
        constexpr int HEND = (A0 < X1 + 1) ? A0 : (X1 + 1);
        #pragma unroll
        for (int x = X0; x < HEND; ++x) val += nbt[x];
        constexpr int NB4 = (A0 <= X1) ? ((X1 + 1 - A0) / 4) : 0;
        #pragma unroll
        for (int c = 0; c < NB4; ++c) {
            float4 f = *(const float4*)(nbt + A0 + 4 * c);
            val += f.x; val += f.y; val += f.z; val += f.w;
        }
        #pragma unroll
        for (int x = A0 + 4 * NB4; x <= X1; ++x) val += nbt[x];
    }
    return val;
}

template<int R>
__device__ __forceinline__ void p1b_row(float* sm, const float* nbt, int b, int t,
                                        int po, int li, int lastLi) {
    float val = chain<1, R>(nbt, sm[po + lastLi - R]);   // = delta(t+R)[last_i]
    sm[OFF_L + R * 96 + li] = val;
    g_plbuf[b][t + R + 1][li] = val;
}

template<int WG, int W>
__device__ __forceinline__ void p1b_grp(float* sm, const float* nbt, int b, int t,
                                        int po, int li, int lastLi) {
    if constexpr (WG < W)      p1b_row<WG>(sm, nbt, b, t, po, li, lastLi);
    if constexpr (WG + 8 < W)  p1b_row<WG + 8>(sm, nbt, b, t, po, li, lastLi);
    if constexpr (WG + 16 < W) p1b_row<WG + 16>(sm, nbt, b, t, po, li, lastLi);
    if constexpr (WG + 24 < W) p1b_row<WG + 24>(sm, nbt, b, t, po, li, lastLi);
}

template<int P, int W>
__device__ __forceinline__ void p3_out(float* sm, const float* nbt,
                                       int no, int li, int baseLi) {
    float val = chain<W - P + 1, W>(nbt, sm[OFF_VF + (W - 1 - P) * 96 + li]);
    sm[no + baseLi + P] = val;
}

template<int WG, int W>
__device__ __forceinline__ void p3_grp(float* sm, const float* nbt,
                                       int no, int li, int baseLi) {
    if constexpr (WG < W)      p3_out<WG, W>(sm, nbt, no, li, baseLi);
    if constexpr (WG + 8 < W)  p3_out<WG + 8, W>(sm, nbt, no, li, baseLi);
    if constexpr (WG + 16 < W) p3_out<WG + 16, W>(sm, nbt, no, li, baseLi);
    if constexpr (WG + 24 < W) p3_out<WG + 24, W>(sm, nbt, no, li, baseLi);
}

template<int W>
__device__ __forceinline__ void do_window(float* sm, int b, int t, int po, int no,
        int tid, int wrp, int wgrp, int li, int lastLi, int baseLi,
        int rj, int rg, const float* tlr)
{
    __syncthreads();   // prev window complete in po
    const float* nbt = sm + OFF_NB + t;   // 16B aligned: t % 4 == 0

    // ---- P1a: bulk shift-by-W, packed f32x2, unconditional stores ----
    {
        float l0 = sm[po + tid              - W], l1 = sm[po + tid + 1*NTHREADS - W];
        float l2 = sm[po + tid + 2*NTHREADS - W], l3 = sm[po + tid + 3*NTHREADS - W];
        float l4 = sm[po + tid + 4*NTHREADS - W], l5 = sm[po + tid + 5*NTHREADS - W];
        float l6 = sm[po + tid + 6*NTHREADS - W], l7 = sm[po + tid + 7*NTHREADS - W];
        uint64_t y0, y1, y2, y3;
        PACK2(y0, l0, l1); PACK2(y1, l2, l3); PACK2(y2, l4, l5); PACK2(y3, l6, l7);
        #pragma unroll
        for (int r = 1; r <= W; ++r) {
            uint64_t nb2 = *(const uint64_t*)&sm[OFF_ND + 2 * (t + r)];
            ADD2(y0, y0, nb2); ADD2(y1, y1, nb2); ADD2(y2, y2, nb2); ADD2(y3, y3, nb2);
        }
        UNPACK2(l0, l1, y0); UNPACK2(l2, l3, y1);
        UNPACK2(l4, l5, y2); UNPACK2(l6, l7, y3);
        sm[no + tid             ] = l0;  sm[no + tid + 1*NTHREADS] = l1;
        sm[no + tid + 2*NTHREADS] = l2;  sm[no + tid + 3*NTHREADS] = l3;
        sm[no + tid + 4*NTHREADS] = l4;  sm[no + tid + 5*NTHREADS] = l5;
        sm[no + tid + 6*NTHREADS] = l6;  sm[no + tid + 7*NTHREADS] = l7;
    }
    // ---- P1b: L-table rows, static chains ----
    if (li < NI) {
        switch (wgrp) {
            case 0: p1b_grp<0, W>(sm, nbt, b, t, po, li, lastLi); break;
            case 1: p1b_grp<1, W>(sm, nbt, b, t, po, li, lastLi); break;
            case 2: p1b_grp<2, W>(sm, nbt, b, t, po, li, lastLi); break;
            case 3: p1b_grp<3, W>(sm, nbt, b, t, po, li, lastLi); break;
            case 4: p1b_grp<4, W>(sm, nbt, b, t, po, li, lastLi); break;
            case 5: p1b_grp<5, W>(sm, nbt, b, t, po, li, lastLi); break;
            case 6: p1b_grp<6, W>(sm, nbt, b, t, po, li, lastLi); break;
            default: p1b_grp<7, W>(sm, nbt, b, t, po, li, lastLi); break;
        }
    }
    __syncthreads();   // L table + bulk cells ready

    // ---- P2: W reductions; leaders store raw vf(+blp) ----
    if (wrp < 21) {
        #pragma unroll 7
        for (int q = 1; q <= W; ++q) {
            const float* Lr = &sm[OFF_L + (q - 1) * 96 + 12 * rg];
            const float4 a0 = *(const float4*)(Lr);
            const float4 a1 = *(const float4*)(Lr + 4);
            const float4 a2 = *(const float4*)(Lr + 8);
            float c0 = a0.x + tlr[0],  c1 = a0.y + tlr[1];
            float c2 = a0.z + tlr[2],  c3 = a0.w + tlr[3];
            c0 = fmaxf(c0, a1.x + tlr[4]);  c1 = fmaxf(c1, a1.y + tlr[5]);
            c2 = fmaxf(c2, a1.z + tlr[6]);  c3 = fmaxf(c3, a1.w + tlr[7]);
            c0 = fmaxf(c0, a2.x + tlr[8]);  c1 = fmaxf(c1, a2.y + tlr[9]);
            c2 = fmaxf(c2, a2.z + tlr[10]); c3 = fmaxf(c3, a2.w + tlr[11]);
            float best = fmaxf(fmaxf(c0, c1), fmaxf(c2, c3));
            best = fmaxf(best, __shfl_xor_sync(0xffffffffu, best, 1));
            best = fmaxf(best, __shfl_xor_sync(0xffffffffu, best, 2));
            best = fmaxf(best, __shfl_xor_sync(0xffffffffu, best, 4));
            if (rg == 0)   // rj<=83: pad columns of VF absorb rj 82/83
                sm[OFF_VF + (q - 1) * 96 + rj] = best + sm[OFF_BLP + t + q];
        }
    }
    __syncthreads();   // vf_raw ready

    // ---- P3: pos<W output cells, static suffix chains ----
    if (li < NI) {
        switch (wgrp) {
            case 0: p3_grp<0, W>(sm, nbt, no, li, baseLi); break;
            case 1: p3_grp<1, W>(sm, nbt, no, li, baseLi); break;
            case 2: p3_grp<2, W>(sm, nbt, no, li, baseLi); break;
            case 3: p3_grp<3, W>(sm, nbt, no, li, baseLi); break;
            case 4: p3_grp<4, W>(sm, nbt, no, li, baseLi); break;
            case 5: p3_grp<5, W>(sm, nbt, no, li, baseLi); break;
            case 6: p3_grp<6, W>(sm, nbt, no, li, baseLi); break;
            default: p3_grp<7, W>(sm, nbt, no, li, baseLi); break;
        }
    }
}

__global__ void __launch_bounds__(NTHREADS, 1)
dbn_viterbi_kernel(const float* __restrict__ logit, float* __restrict__ out)
{
    extern __shared__ float sm[];
    const int tid  = threadIdx.x;
    const int wrp  = tid >> 5;
    const int b    = blockIdx.x;
    const float* lg = logit + b * TT;
    float* outrow   = out + b * TT;

    const float NEGINF = __int_as_float(0xff800000);

    // ---- zero output row ----
    for (int t = tid; t < TT; t += NTHREADS) outrow[t] = 0.0f;

    // ---- emissions (double precision, cast to f32; bit-matched reference) ----
    for (int t = tid; t < TT; t += NTHREADS) {
        double x = (double)lg[t];
        double bl = (x >= 0.0) ? -log1p(exp(-x)) : (x - log1p(exp(x)));
        double nl = (x <= 0.0) ? -log1p(exp(x))  : (-x - log1p(exp(-x)));
        float nlf = (float)nl;
        sm[OFF_BLP + t] = (float)bl;
        sm[OFF_NB  + t] = nlf;
        sm[OFF_ND + 2 * t]     = nlf;   // packed duplicate for f32x2 bulk
        sm[OFF_ND + 2 * t + 1] = nlf;
    }

    // ---- trans_log rows (double precision log-softmax) ----
    if (tid < NI) {
        int i = tid;
        double ti = (double)(MINTAU + i);
        double ssum = 0.0;
        for (int j = 0; j < NI; ++j) {
            double r = -100.0 * fabs((double)(MINTAU + j) / ti - 1.0);
            ssum += exp(r);
        }
        double ls = log(ssum);  // row max is 0 (at j==i)
        for (int j = 0; j < NI; ++j) {
            double r = -100.0 * fabs((double)(MINTAU + j) / ti - 1.0);
            sm[OFF_TL + i * NI + j] = (float)(r - ls);
        }
    }
    // -inf pads for all L rows (cols 82..95), set once (P1b writes cols<82 only)
    if (tid < WIN * 14) {
        int row = tid / 14, c = tid % 14;
        sm[OFF_L + row * 96 + 82 + c] = NEGINF;
    }

    // ---- per-slot masks (argmax validity + init first-state) ----
    unsigned firstM = 0, validM = 0;
    #pragma unroll
    for (int k = 0; k < 8; ++k) {
        int s = tid + k * NTHREADS;
        int j = 0;
        while (j < NI - 1 && base_of(j + 1) <= s) ++j;
        int pos = s - base_of(j);
        if (s < NSTATE) {
            validM |= 1u << k;
            if (pos == 0) firstM |= 1u << k;
        }
    }

    // per-thread roles
    const int wgrp   = tid / 96;                     // 0..7 (3 warps per group)
    const int li     = tid - 96 * wgrp;              // 0..95
    const int lastLi = (li < NI) ? (base_of(li + 1) - 1) : 0;
    const int baseLi = (li < NI) ? base_of(li) : 0;
    const int rj = tid >> 3, rg = tid & 7;           // reduction: 8 lanes per j

    const float logS = (float)log((double)NSTATE);

    __syncthreads();   // tables ready

    // ---- preload trans_log candidates: contiguous block i in [12rg, 12rg+12) ----
    float tlr[12];
    #pragma unroll
    for (int c = 0; c < 12; ++c) {
        int i = 12 * rg + c;
        tlr[c] = (rj < NI && i < NI) ? sm[OFF_TL + i * NI + rj] : 0.0f;  // L pad = -inf
    }

    // ---- init delta(0) into buffer A ----
    {
        float bt0 = sm[OFF_BLP + 0], nbt0 = sm[OFF_NB + 0];
        #pragma unroll
        for (int k = 0; k < 8; ++k) {
            int s = tid + k * NTHREADS;
            float em = ((firstM >> k) & 1u) ? bt0 : nbt0;
            sm[OFF_A + s] = em - logS;   // pads finite, harmless
        }
    }

    // ---- forward: 214 windows of 28 + tail of 7 ----
    int po = OFF_A, no = OFF_B;
    #pragma unroll 1
    for (int wnd = 0; wnd < NWIN; ++wnd) {
        do_window<WIN>(sm, b, wnd * WIN, po, no, tid, wrp, wgrp, li,
                       lastLi, baseLi, rj, rg, tlr);
        int tmp = po; po = no; no = tmp;
    }
    // po = OFF_A after 214 swaps; tail -> delta(5999) in OFF_B
    do_window<TAILW>(sm, b, NWIN * WIN, po, no, tid, wrp, wgrp, li,
                     lastLi, baseLi, rj, rg, tlr);
    __syncthreads();

    // ---- final argmax over delta(5999) in OFF_B, first-index tiebreak ----
    {
        float bv = NEGINF; int bs = NSTATE - 1;
        #pragma unroll
        for (int k = 0; k < 8; ++k) {
            if ((validM >> k) & 1u) {
                int s = tid + k * NTHREADS;
                float val = sm[OFF_B + s];
                if (val > bv) { bv = val; bs = s; }
            }
        }
        sm[OFF_RV + tid] = bv;
        ((int*)sm)[OFF_RI + tid] = bs;
    }
    __syncthreads();
    if (tid < NTHREADS - 512) {   // fold 512..767 into 0..255
        float v2 = sm[OFF_RV + tid + 512]; int s2 = ((int*)sm)[OFF_RI + tid + 512];
        if (v2 > sm[OFF_RV + tid] ||
            (v2 == sm[OFF_RV + tid] && s2 < ((int*)sm)[OFF_RI + tid])) {
            sm[OFF_RV + tid] = v2; ((int*)sm)[OFF_RI + tid] = s2;
        }
    }
    __syncthreads();
    for (int st = 256; st > 0; st >>= 1) {
        if (tid < st) {
            float v2 = sm[OFF_RV + tid + st]; int s2 = ((int*)sm)[OFF_RI + tid + st];
            if (v2 > sm[OFF_RV + tid] ||
                (v2 == sm[OFF_RV + tid] && s2 < ((int*)sm)[OFF_RI + tid])) {
                sm[OFF_RV + tid] = v2; ((int*)sm)[OFF_RI + tid] = s2;
            }
        }
        __syncthreads();
    }

    // ---- backtrack (thread 0): jump beat-to-beat, hard-bounded ----
    if (tid == 0) {
        const double p0  = (double)0.05f;
        const double thr = log(p0 / (1.0 - p0));   // logit-space threshold

        int s = ((int*)sm)[OFF_RI + 0];
        if (s < 0) s = 0;
        if (s >= NSTATE) s = NSTATE - 1;
        int j = 0;
        while (j < NI - 1 && base_of(j + 1) <= s) ++j;
        int p = s - base_of(j);
        int t = TT - 1;
        for (int iter = 0; iter < TT; ++iter) {
            if (p > t) break;            // path started mid-block: no beat
            int tb = t - p;              // beat time (position 0)
            double x = (double)lg[tb];
            outrow[tb] = (x >= thr) ? 1.0f : 0.0f;
            if (tb == 0) break;
            const float* row = &g_plbuf[b][tb][0];
            float mx = NEGINF; int bi = 0;
            for (int i = 0; i < NI; ++i) {
                float c = row[i] + sm[OFF_TL + i * NI + j];
                if (c > mx) { mx = c; bi = i; }
            }
            j = bi;
            t = tb - 1;
            p = (MINTAU + j) - 1;
        }
    }
}

extern "C" void kernel_launch(void* const* d_in, const int* in_sizes, int n_in,
                              void* d_out, int out_size)
{
    const float* logit = (const float*)d_in[0];
    float* out = (float*)d_out;

    size_t smem = (size_t)SM_FLOATS * sizeof(float);   // 199,808 B
    cudaFuncSetAttribute(dbn_viterbi_kernel,
                         cudaFuncAttributeMaxDynamicSharedMemorySize, (int)smem);
    dbn_viterbi_kernel<<<BB, NTHREADS, smem>>>(logit, out);
}